// round 1
// baseline (speedup 1.0000x reference)
#include <cuda_runtime.h>
#include <math.h>

// Problem constants
#define NB    16
#define NH    16
#define LSEQ  1024
#define DMODEL 1024
#define NMODES 64
#define NDK   64
// "ft" tensors stored as (b, 128, 1024): rows 0..63 = real(mode m), rows 64..127 = imag(mode m)

// -------------------- scratch (static device memory; no allocs) --------------------
__device__ float g_q  [(size_t)NB * LSEQ * DMODEL];
__device__ float g_k  [(size_t)NB * LSEQ * DMODEL];
__device__ float g_v  [(size_t)NB * LSEQ * DMODEL];
__device__ float g_tm [(size_t)NB * LSEQ * DMODEL];
__device__ float g_qft[(size_t)NB * 128 * DMODEL];
__device__ float g_kft[(size_t)NB * 128 * DMODEL];
__device__ float g_vft[(size_t)NB * 128 * DMODEL];
__device__ float g_oft[(size_t)NB * 128 * DMODEL];
__device__ float g_F  [128 * 1024];   // forward DFT:  rows m: cos, rows 64+m: -sin
__device__ float g_G  [1024 * 128];   // inverse:      cols m: (m==0?1:2cos)/N, cols 64+m: -2sin/N

// -------------------- twiddle init --------------------
__global__ void init_twiddles() {
    int idx = blockIdx.x * blockDim.x + threadIdx.x;   // 0 .. 65535
    int m = idx >> 10;
    int l = idx & 1023;
    int t = (m * l) & 1023;
    double ang = (double)t * (6.283185307179586476925286766559 / 1024.0);
    double c = cos(ang), s = sin(ang);
    g_F[m * 1024 + l]        = (float)c;
    g_F[(64 + m) * 1024 + l] = (float)(-s);
    g_G[l * 128 + m]      = (m == 0) ? (1.0f / 1024.0f) : (float)(2.0 * c / 1024.0);
    g_G[l * 128 + 64 + m] = (m == 0) ? 0.0f             : (float)(-2.0 * s / 1024.0);
}

// -------------------- generic tiled fp32 GEMM: C = A(MxK) @ B(KxN) [+ bias] --------------------
// BM=BN=128, BK=8, 256 threads, 8x8 per thread. Requires M%128==0, N%128==0, K%8==0.
// blockIdx.z = batch; sA/sB/sC are element strides between batches (0 = shared operand).
__global__ __launch_bounds__(256) void gemm128(
    const float* __restrict__ A, const float* __restrict__ B,
    const float* __restrict__ bias, float* __restrict__ C,
    int M, int N, int K,
    long long sA, long long sB, long long sC)
{
    __shared__ float As[8][128];
    __shared__ float Bs[8][128];

    const int bz = blockIdx.z;
    A += (size_t)bz * (size_t)sA;
    B += (size_t)bz * (size_t)sB;
    C += (size_t)bz * (size_t)sC;

    const int tid  = threadIdx.x;
    const int row0 = blockIdx.y * 128;
    const int col0 = blockIdx.x * 128;
    const int tm = (tid >> 4) << 3;   // 0,8,...,120
    const int tn = (tid & 15) << 3;   // 0,8,...,120

    const int la_row = tid >> 1;            // 0..127
    const int la_col = (tid & 1) << 2;      // 0 or 4
    const int lb_row = tid >> 5;            // 0..7
    const int lb_col = (tid & 31) << 2;     // 0,4,...,124

    const float* Aptr = A + (size_t)(row0 + la_row) * K + la_col;
    const float* Bptr = B + (size_t)lb_row * N + col0 + lb_col;

    float acc[8][8];
    #pragma unroll
    for (int i = 0; i < 8; i++)
        #pragma unroll
        for (int j = 0; j < 8; j++) acc[i][j] = 0.0f;

    for (int k0 = 0; k0 < K; k0 += 8) {
        float4 av = *(const float4*)(Aptr + k0);
        float4 bv = *(const float4*)(Bptr + (size_t)k0 * N);
        __syncthreads();
        As[la_col + 0][la_row] = av.x;
        As[la_col + 1][la_row] = av.y;
        As[la_col + 2][la_row] = av.z;
        As[la_col + 3][la_row] = av.w;
        *(float4*)&Bs[lb_row][lb_col] = bv;
        __syncthreads();

        #pragma unroll
        for (int kk = 0; kk < 8; kk++) {
            float a[8], b[8];
            #pragma unroll
            for (int i = 0; i < 8; i++) a[i] = As[kk][tm + i];
            #pragma unroll
            for (int j = 0; j < 8; j++) b[j] = Bs[kk][tn + j];
            #pragma unroll
            for (int i = 0; i < 8; i++)
                #pragma unroll
                for (int j = 0; j < 8; j++)
                    acc[i][j] = fmaf(a[i], b[j], acc[i][j]);
        }
    }

    float bb[8];
    #pragma unroll
    for (int j = 0; j < 8; j++) bb[j] = bias ? bias[col0 + tn + j] : 0.0f;

    #pragma unroll
    for (int i = 0; i < 8; i++) {
        float* cp = C + (size_t)(row0 + tm + i) * N + col0 + tn;
        float4 v0, v1;
        v0.x = acc[i][0] + bb[0]; v0.y = acc[i][1] + bb[1];
        v0.z = acc[i][2] + bb[2]; v0.w = acc[i][3] + bb[3];
        v1.x = acc[i][4] + bb[4]; v1.y = acc[i][5] + bb[5];
        v1.z = acc[i][6] + bb[6]; v1.w = acc[i][7] + bb[7];
        *(float4*)cp       = v0;
        *(float4*)(cp + 4) = v1;
    }
}

// -------------------- Fourier attention: one CTA per (b,h) --------------------
// attn = Qr@Kr^T + Qi@Ki^T ; softmax rows ; Or = attn@Vr ; Oi = attn@Vi
__global__ __launch_bounds__(256) void fourier_attn() {
    __shared__ float As[64][65];
    __shared__ float Bs[64][65];

    const int b = blockIdx.x >> 4;
    const int h = blockIdx.x & 15;
    const float* qft = g_qft + (size_t)b * 128 * DMODEL;
    const float* kft = g_kft + (size_t)b * 128 * DMODEL;
    const float* vft = g_vft + (size_t)b * 128 * DMODEL;
    float*       oft = g_oft + (size_t)b * 128 * DMODEL;

    const int tid = threadIdx.x;
    const int m   = tid >> 2;          // attn row 0..63
    const int sc  = (tid & 3) << 4;    // 16-wide column group
    const size_t hoff = (size_t)h * NDK;

    float acc[16];
    #pragma unroll
    for (int j = 0; j < 16; j++) acc[j] = 0.0f;

    // QK^T, real then imag pass
    for (int p = 0; p < 2; p++) {
        const int roff = p * 64;
        __syncthreads();
        for (int i = tid; i < 4096; i += 256) {
            int r = i >> 6, c = i & 63;
            As[r][c] = qft[(size_t)(roff + r) * DMODEL + hoff + c];
            Bs[r][c] = kft[(size_t)(roff + r) * DMODEL + hoff + c];
        }
        __syncthreads();
        #pragma unroll 8
        for (int dk = 0; dk < 64; dk++) {
            float qv = As[m][dk];
            #pragma unroll
            for (int j = 0; j < 16; j++)
                acc[j] = fmaf(qv, Bs[sc + j][dk], acc[j]);
        }
    }

    // softmax across row (4 threads per row, contiguous lanes -> xor 1,2 stays in quad)
    float mx = acc[0];
    #pragma unroll
    for (int j = 1; j < 16; j++) mx = fmaxf(mx, acc[j]);
    mx = fmaxf(mx, __shfl_xor_sync(0xffffffffu, mx, 1));
    mx = fmaxf(mx, __shfl_xor_sync(0xffffffffu, mx, 2));
    float sum = 0.0f;
    #pragma unroll
    for (int j = 0; j < 16; j++) { acc[j] = expf(acc[j] - mx); sum += acc[j]; }
    sum += __shfl_xor_sync(0xffffffffu, sum, 1);
    sum += __shfl_xor_sync(0xffffffffu, sum, 2);
    float inv = 1.0f / sum;
    #pragma unroll
    for (int j = 0; j < 16; j++) acc[j] *= inv;

    __syncthreads();                       // everyone done reading As/Bs
    #pragma unroll
    for (int j = 0; j < 16; j++) As[m][sc + j] = acc[j];   // attn -> As

    // attn @ V, real then imag pass (As holds attn throughout)
    for (int p = 0; p < 2; p++) {
        const int roff = p * 64;
        if (p) __syncthreads();            // done reading Bs before rewrite
        for (int i = tid; i < 4096; i += 256) {
            int r = i >> 6, c = i & 63;
            Bs[r][c] = vft[(size_t)(roff + r) * DMODEL + hoff + c];
        }
        __syncthreads();
        float o[16];
        #pragma unroll
        for (int j = 0; j < 16; j++) o[j] = 0.0f;
        #pragma unroll 8
        for (int s = 0; s < 64; s++) {
            float a = As[m][s];
            #pragma unroll
            for (int j = 0; j < 16; j++)
                o[j] = fmaf(a, Bs[s][sc + j], o[j]);
        }
        #pragma unroll
        for (int j = 0; j < 16; j++)
            oft[(size_t)(roff + m) * DMODEL + hoff + sc + j] = o[j];
    }
}

// -------------------- launch --------------------
extern "C" void kernel_launch(void* const* d_in, const int* in_sizes, int n_in,
                              void* d_out, int out_size) {
    const float* queries = (const float*)d_in[0];
    const float* keys    = (const float*)d_in[1];
    const float* values  = (const float*)d_in[2];
    const float* Wq = (const float*)d_in[3];
    const float* bq = (const float*)d_in[4];
    const float* Wk = (const float*)d_in[5];
    const float* bk = (const float*)d_in[6];
    const float* Wv = (const float*)d_in[7];
    const float* bv = (const float*)d_in[8];
    const float* Wo = (const float*)d_in[9];
    const float* bo = (const float*)d_in[10];
    float* out = (float*)d_out;

    float *q, *k, *v, *tm, *qft, *kft, *vft, *oft, *F, *G;
    cudaGetSymbolAddress((void**)&q,   g_q);
    cudaGetSymbolAddress((void**)&k,   g_k);
    cudaGetSymbolAddress((void**)&v,   g_v);
    cudaGetSymbolAddress((void**)&tm,  g_tm);
    cudaGetSymbolAddress((void**)&qft, g_qft);
    cudaGetSymbolAddress((void**)&kft, g_kft);
    cudaGetSymbolAddress((void**)&vft, g_vft);
    cudaGetSymbolAddress((void**)&oft, g_oft);
    cudaGetSymbolAddress((void**)&F,   g_F);
    cudaGetSymbolAddress((void**)&G,   g_G);

    const int M  = NB * LSEQ;   // 16384
    const int D  = DMODEL;      // 1024

    init_twiddles<<<256, 256>>>();

    // QKV projections: (16384x1024) @ (1024x1024) + bias
    gemm128<<<dim3(8, 128, 1), 256>>>(queries, Wq, bq, q, M, D, D, 0, 0, 0);
    gemm128<<<dim3(8, 128, 1), 256>>>(keys,    Wk, bk, k, M, D, D, 0, 0, 0);
    gemm128<<<dim3(8, 128, 1), 256>>>(values,  Wv, bv, v, M, D, D, 0, 0, 0);

    // Truncated rfft as GEMM: (128x1024) @ (1024x1024) per batch
    const long long sQ = (long long)LSEQ * D;       // 1024*1024
    const long long sF = (long long)128 * D;        // 128*1024
    gemm128<<<dim3(8, 1, NB), 256>>>(F, q, nullptr, qft, 128, D, LSEQ, 0, sQ, sF);
    gemm128<<<dim3(8, 1, NB), 256>>>(F, k, nullptr, kft, 128, D, LSEQ, 0, sQ, sF);
    gemm128<<<dim3(8, 1, NB), 256>>>(F, v, nullptr, vft, 128, D, LSEQ, 0, sQ, sF);

    // Per-(b,h) complex-real attention + softmax
    fourier_attn<<<NB * NH, 256>>>();

    // Truncated irfft as GEMM: (1024x128) @ (128x1024) per batch
    gemm128<<<dim3(8, 8, NB), 256>>>(G, oft, nullptr, tm, LSEQ, D, 128, 0, sF, sQ);

    // Output projection
    gemm128<<<dim3(8, 128, 1), 256>>>(tm, Wo, bo, out, M, D, D, 0, 0, 0);
}